// round 3
// baseline (speedup 1.0000x reference)
#include <cuda_runtime.h>
#include <math.h>
#include <stdint.h>

#define BATCH  8
#define SEQ    2048
#define MTOT   (BATCH*SEQ)      // 16384
#define DIN    64
#define HID    256
#define DMODEL 512
#define DINNER 1024
#define DSTATE 16
#define DTRANK 32
#define DCONV  4
#define DOUTD  64

// ---------------- scratch (allocation-free, __device__ globals) ----------------
__device__ float g_h    [MTOT*HID];
__device__ float g_u    [MTOT*DMODEL];
__device__ float g_xz   [MTOT*2*DINNER];   // (xm | z)
__device__ float g_xm   [MTOT*DINNER];
__device__ float g_dbl  [MTOT*64];         // [dt(32)|B(16)|C(16)]
__device__ float g_delta[MTOT*DINNER];
__device__ float g_y    [MTOT*DINNER];     // scan+gate out
__device__ float g_o1   [MTOT*DMODEL];
__device__ float g_h2   [MTOT*HID];

enum Act { ACT_NONE = 0, ACT_RELU = 1, ACT_SOFTPLUS = 2 };

// ---------------- helpers ----------------
__device__ __forceinline__ float to_tf32(float x) {
    float r;
    asm("cvt.rna.tf32.f32 %0, %1;" : "=f"(r) : "f"(x));
    return r;
}

__device__ __forceinline__ void mma8(float c[4], const uint32_t a[4], const uint32_t b[2]) {
    asm volatile(
        "mma.sync.aligned.m16n8k8.row.col.f32.tf32.tf32.f32 "
        "{%0,%1,%2,%3}, {%4,%5,%6,%7}, {%8,%9}, {%0,%1,%2,%3};\n"
        : "+f"(c[0]), "+f"(c[1]), "+f"(c[2]), "+f"(c[3])
        : "r"(a[0]), "r"(a[1]), "r"(a[2]), "r"(a[3]),
          "r"(b[0]), "r"(b[1]));
}

__device__ __forceinline__ void cp16(void* smem_dst, const void* gsrc) {
    uint32_t d = (uint32_t)__cvta_generic_to_shared(smem_dst);
    asm volatile("cp.async.cg.shared.global [%0], [%1], 16;\n" :: "r"(d), "l"(gsrc));
}
__device__ __forceinline__ void cp_commit() { asm volatile("cp.async.commit_group;\n"); }
__device__ __forceinline__ void cp_wait0()  { asm volatile("cp.async.wait_group 0;\n"); }
__device__ __forceinline__ void cp_wait1()  { asm volatile("cp.async.wait_group 1;\n"); }

// ---------------- cp.async double-buffered tensor-core GEMM ----------------
// C[M,N] = act(A[M,K(lda)] * W[N,K]^T + bias)
// SPLIT=0: plain tf32.  SPLIT=1: tf32x3 (hi/lo split, fp32-class accuracy).
// Conversion to tf32 happens at fragment-load time (smem holds raw fp32).
template<int BM,int BN,int WARPS_M,int WARPS_N,int ACT,int SPLIT>
__global__ void __launch_bounds__(WARPS_M*WARPS_N*32)
gemm_tc(const float* __restrict__ A, const float* __restrict__ W,
        const float* __restrict__ bias, float* __restrict__ C,
        int M, int N, int K, int lda)
{
    constexpr int BK = 32, SK = BK + 4;
    constexpr int THREADS = WARPS_M*WARPS_N*32;
    constexpr int WM = BM/WARPS_M, WN = BN/WARPS_N;
    constexpr int MM = WM/16, MN = WN/8;

    extern __shared__ float sm[];
    float* sA = sm;               // [2][BM*SK]
    float* sB = sm + 2*BM*SK;     // [2][BN*SK]

    const int tid  = threadIdx.x;
    const int lane = tid & 31;
    const int warp = tid >> 5;
    const int g    = lane >> 2;
    const int c4   = lane & 3;
    const int wrow = (warp / WARPS_N) * WM;
    const int wcol = (warp % WARPS_N) * WN;
    const int bm   = blockIdx.y * BM;
    const int bn   = blockIdx.x * BN;

    float acc[MM][MN][4];
#pragma unroll
    for (int i = 0; i < MM; i++)
#pragma unroll
        for (int j = 0; j < MN; j++)
#pragma unroll
            for (int q = 0; q < 4; q++) acc[i][j][q] = 0.f;

    const int KT = K / BK;

    // stage loader
    auto load_stage = [&](int buf, int k0) {
        float* dA = sA + buf*BM*SK;
#pragma unroll
        for (int i = tid; i < BM*(BK/4); i += THREADS) {
            int m  = i / (BK/4);
            int kc = (i % (BK/4)) * 4;
            cp16(dA + m*SK + kc, A + (size_t)(bm + m)*lda + k0 + kc);
        }
        float* dB = sB + buf*BN*SK;
#pragma unroll
        for (int i = tid; i < BN*(BK/4); i += THREADS) {
            int n  = i / (BK/4);
            int kc = (i % (BK/4)) * 4;
            cp16(dB + n*SK + kc, W + (size_t)(bn + n)*K + k0 + kc);
        }
    };

    load_stage(0, 0);
    cp_commit();

    for (int kt = 0; kt < KT; kt++) {
        if (kt + 1 < KT) {
            load_stage((kt + 1) & 1, (kt + 1) * BK);
            cp_commit();
            cp_wait1();
        } else {
            cp_wait0();
        }
        __syncthreads();

        const float* bA = sA + (kt & 1)*BM*SK;
        const float* bB = sB + (kt & 1)*BN*SK;

#pragma unroll
        for (int kk = 0; kk < BK; kk += 8) {
            uint32_t ah[MM][4], al[MM][4];
#pragma unroll
            for (int mi = 0; mi < MM; mi++) {
                const float* p = bA + (wrow + mi*16 + g)*SK + kk + c4;
                float r0 = p[0], r1 = p[8*SK], r2 = p[4], r3 = p[8*SK + 4];
                float h0 = to_tf32(r0), h1 = to_tf32(r1), h2 = to_tf32(r2), h3 = to_tf32(r3);
                ah[mi][0] = __float_as_uint(h0); ah[mi][1] = __float_as_uint(h1);
                ah[mi][2] = __float_as_uint(h2); ah[mi][3] = __float_as_uint(h3);
                if (SPLIT) {
                    al[mi][0] = __float_as_uint(to_tf32(r0 - h0));
                    al[mi][1] = __float_as_uint(to_tf32(r1 - h1));
                    al[mi][2] = __float_as_uint(to_tf32(r2 - h2));
                    al[mi][3] = __float_as_uint(to_tf32(r3 - h3));
                }
            }
            uint32_t bh[MN][2], bl[MN][2];
#pragma unroll
            for (int ni = 0; ni < MN; ni++) {
                const float* p = bB + (wcol + ni*8 + g)*SK + kk + c4;
                float r0 = p[0], r1 = p[4];
                float h0 = to_tf32(r0), h1 = to_tf32(r1);
                bh[ni][0] = __float_as_uint(h0);
                bh[ni][1] = __float_as_uint(h1);
                if (SPLIT) {
                    bl[ni][0] = __float_as_uint(to_tf32(r0 - h0));
                    bl[ni][1] = __float_as_uint(to_tf32(r1 - h1));
                }
            }
#pragma unroll
            for (int ni = 0; ni < MN; ni++)
#pragma unroll
                for (int mi = 0; mi < MM; mi++) {
                    if (SPLIT) {
                        mma8(acc[mi][ni], al[mi], bh[ni]);
                        mma8(acc[mi][ni], ah[mi], bl[ni]);
                    }
                    mma8(acc[mi][ni], ah[mi], bh[ni]);
                }
        }
        __syncthreads();
    }

    // epilogue
#pragma unroll
    for (int mi = 0; mi < MM; mi++) {
        int r0 = bm + wrow + mi*16 + g;
#pragma unroll
        for (int ni = 0; ni < MN; ni++) {
            int col = bn + wcol + ni*8 + 2*c4;
            float b0 = 0.f, b1 = 0.f;
            if (bias) { b0 = bias[col]; b1 = bias[col + 1]; }
            float v0 = acc[mi][ni][0] + b0;
            float v1 = acc[mi][ni][1] + b1;
            float v2 = acc[mi][ni][2] + b0;
            float v3 = acc[mi][ni][3] + b1;
            if (ACT == ACT_RELU) {
                v0 = fmaxf(v0, 0.f); v1 = fmaxf(v1, 0.f);
                v2 = fmaxf(v2, 0.f); v3 = fmaxf(v3, 0.f);
            }
            if (ACT == ACT_SOFTPLUS) {
                v0 = (v0 > 20.f) ? v0 : log1pf(__expf(v0));
                v1 = (v1 > 20.f) ? v1 : log1pf(__expf(v1));
                v2 = (v2 > 20.f) ? v2 : log1pf(__expf(v2));
                v3 = (v3 > 20.f) ? v3 : log1pf(__expf(v3));
            }
            *(float2*)(C + (size_t)r0*N + col)       = make_float2(v0, v1);
            *(float2*)(C + (size_t)(r0 + 8)*N + col) = make_float2(v2, v3);
        }
    }
}

// ---------------- depthwise causal conv1d (k=4) + bias + SiLU, float4 over channels ----------------
__global__ void conv_silu_kernel(const float* __restrict__ conv_w,
                                 const float* __restrict__ conv_b)
{
    int idx = blockIdx.x * blockDim.x + threadIdx.x;
    if (idx >= MTOT * (DINNER/4)) return;
    int d4 = (idx % (DINNER/4)) * 4;
    int bt = idx / (DINNER/4);
    int t  = bt % SEQ;
    int b  = bt / SEQ;

    float4 acc = *(const float4*)(conv_b + d4);
    float w[4][4];
#pragma unroll
    for (int c = 0; c < 4; c++)
#pragma unroll
        for (int j = 0; j < 4; j++) w[c][j] = conv_w[(d4 + c)*DCONV + j];

#pragma unroll
    for (int j = 0; j < DCONV; j++) {
        int tt = t - (DCONV - 1) + j;
        if (tt >= 0) {
            float4 v = *(const float4*)(g_xz + (size_t)(b*SEQ + tt)*(2*DINNER) + d4);
            acc.x = fmaf(w[0][j], v.x, acc.x);
            acc.y = fmaf(w[1][j], v.y, acc.y);
            acc.z = fmaf(w[2][j], v.z, acc.z);
            acc.w = fmaf(w[3][j], v.w, acc.w);
        }
    }
    float4 o;
    o.x = acc.x / (1.f + __expf(-acc.x));
    o.y = acc.y / (1.f + __expf(-acc.y));
    o.z = acc.z / (1.f + __expf(-acc.z));
    o.w = acc.w / (1.f + __expf(-acc.w));
    *(float4*)(g_xm + (size_t)bt*DINNER + d4) = o;
}

// ---------------- selective scan + fused gating ----------------
__global__ void scan_kernel(const float* __restrict__ A_log,
                            const float* __restrict__ D_param)
{
    int gid = blockIdx.x * blockDim.x + threadIdx.x;
    int grp = gid >> 4;          // (b,d)
    int s   = gid & 15;
    if (grp >= BATCH * DINNER) return;
    int b = grp / DINNER;
    int d = grp % DINNER;

    const float Av = -__expf(A_log[d*DSTATE + s]);
    const float Dv = D_param[d];
    const float* drow = g_delta + (size_t)b*SEQ*DINNER + d;
    const float* xrow = g_xm    + (size_t)b*SEQ*DINNER + d;
    const float* zrow = g_xz    + (size_t)b*SEQ*(2*DINNER) + DINNER + d;
    const float* dblb = g_dbl   + (size_t)b*SEQ*64;
    float*       yrow = g_y     + (size_t)b*SEQ*DINNER + d;

    float h = 0.f;
    for (int t = 0; t < SEQ; t++) {
        float dt = drow[(size_t)t*DINNER];
        float xt = xrow[(size_t)t*DINNER];
        float Bt = dblb[t*64 + DTRANK + s];
        float Ct = dblb[t*64 + DTRANK + DSTATE + s];
        float dA = __expf(dt * Av);
        h = fmaf(dA, h, dt * xt * Bt);
        float p = h * Ct;
        p += __shfl_xor_sync(0xffffffffu, p, 8, 16);
        p += __shfl_xor_sync(0xffffffffu, p, 4, 16);
        p += __shfl_xor_sync(0xffffffffu, p, 2, 16);
        p += __shfl_xor_sync(0xffffffffu, p, 1, 16);
        if (s == 0) {
            float z  = zrow[(size_t)t*2*DINNER];
            float yv = p + xt * Dv;
            yrow[(size_t)t*DINNER] = yv * (z / (1.f + __expf(-z)));
        }
    }
}

// ---------------- host launch ----------------
static float* sym_addr(const void* symbol)
{
    void* p = nullptr;
    cudaGetSymbolAddress(&p, symbol);
    return (float*)p;
}

extern "C" void kernel_launch(void* const* d_in, const int* in_sizes, int n_in,
                              void* d_out, int out_size)
{
    const float* x         = (const float*)d_in[0];
    const float* enc_w1    = (const float*)d_in[1];
    const float* enc_b1    = (const float*)d_in[2];
    const float* enc_w2    = (const float*)d_in[3];
    const float* enc_b2    = (const float*)d_in[4];
    const float* in_proj_w = (const float*)d_in[5];
    const float* conv_w    = (const float*)d_in[6];
    const float* conv_b    = (const float*)d_in[7];
    const float* x_proj_w  = (const float*)d_in[8];
    const float* dt_proj_w = (const float*)d_in[9];
    const float* dt_proj_b = (const float*)d_in[10];
    const float* A_log     = (const float*)d_in[11];
    const float* D_param   = (const float*)d_in[12];
    const float* out_proj_w= (const float*)d_in[13];
    const float* dec_w1    = (const float*)d_in[14];
    const float* dec_b1    = (const float*)d_in[15];
    const float* dec_w2    = (const float*)d_in[16];
    const float* dec_b2    = (const float*)d_in[17];
    float* out = (float*)d_out;

    float* ph    = sym_addr(g_h);
    float* pu    = sym_addr(g_u);
    float* pxz   = sym_addr(g_xz);
    float* pxm   = sym_addr(g_xm);
    float* pdbl  = sym_addr(g_dbl);
    float* pdel  = sym_addr(g_delta);
    float* py    = sym_addr(g_y);
    float* po1   = sym_addr(g_o1);
    float* ph2   = sym_addr(g_h2);

    // dynamic smem: 2 stages x raw fp32 (A BM rows + B BN rows), stride 36 floats
    const int SMEM_BIG  = 2 * (128 + 128) * 36 * 4;   // 73728
    const int SMEM_NARR = 2 * (128 + 64) * 36 * 4;    // 55296

    cudaFuncSetAttribute(gemm_tc<128,128,2,4,ACT_RELU,1>,
                         cudaFuncAttributeMaxDynamicSharedMemorySize, SMEM_BIG);
    cudaFuncSetAttribute(gemm_tc<128,128,2,4,ACT_NONE,1>,
                         cudaFuncAttributeMaxDynamicSharedMemorySize, SMEM_BIG);
    cudaFuncSetAttribute(gemm_tc<128,128,2,4,ACT_NONE,0>,
                         cudaFuncAttributeMaxDynamicSharedMemorySize, SMEM_BIG);
    cudaFuncSetAttribute(gemm_tc<128,128,2,4,ACT_SOFTPLUS,1>,
                         cudaFuncAttributeMaxDynamicSharedMemorySize, SMEM_BIG);
    cudaFuncSetAttribute(gemm_tc<128,64,4,2,ACT_NONE,1>,
                         cudaFuncAttributeMaxDynamicSharedMemorySize, SMEM_NARR);

    // 1. enc1: relu(x @ enc_w1^T + b1)   [16384,256] K=64   (tf32x3)
    gemm_tc<128,128,2,4,ACT_RELU,1><<<dim3(HID/128, MTOT/128), 256, SMEM_BIG>>>(
        x, enc_w1, enc_b1, ph, MTOT, HID, DIN, DIN);

    // 2. enc2: u = h @ enc_w2^T + b2     [16384,512] K=256  (tf32x3)
    gemm_tc<128,128,2,4,ACT_NONE,1><<<dim3(DMODEL/128, MTOT/128), 256, SMEM_BIG>>>(
        ph, enc_w2, enc_b2, pu, MTOT, DMODEL, HID, HID);

    // 3. in_proj: xz = u @ in_proj_w^T   [16384,2048] K=512 (plain tf32)
    gemm_tc<128,128,2,4,ACT_NONE,0><<<dim3(2*DINNER/128, MTOT/128), 256, SMEM_BIG>>>(
        pu, in_proj_w, nullptr, pxz, MTOT, 2*DINNER, DMODEL, DMODEL);

    // 4. conv + bias + silu -> g_xm
    conv_silu_kernel<<<(MTOT*(DINNER/4))/256, 256>>>(conv_w, conv_b);

    // 5. x_proj: dbl = xm @ x_proj_w^T   [16384,64] K=1024  (tf32x3)
    gemm_tc<128,64,4,2,ACT_NONE,1><<<dim3(1, MTOT/128), 256, SMEM_NARR>>>(
        pxm, x_proj_w, nullptr, pdbl, MTOT, 64, DINNER, DINNER);

    // 6. dt_proj + softplus: delta       [16384,1024] K=32, lda=64 (tf32x3)
    gemm_tc<128,128,2,4,ACT_SOFTPLUS,1><<<dim3(DINNER/128, MTOT/128), 256, SMEM_BIG>>>(
        pdbl, dt_proj_w, dt_proj_b, pdel, MTOT, DINNER, DTRANK, 64);

    // 7. selective scan + fused gating -> g_y
    scan_kernel<<<(BATCH*DINNER*DSTATE)/256, 256>>>(A_log, D_param);

    // 8. out_proj: o1 = y @ out_proj_w^T [16384,512] K=1024 (plain tf32)
    gemm_tc<128,128,2,4,ACT_NONE,0><<<dim3(DMODEL/128, MTOT/128), 256, SMEM_BIG>>>(
        py, out_proj_w, nullptr, po1, MTOT, DMODEL, DINNER, DINNER);

    // 9. dec1: relu                      [16384,256] K=512  (tf32x3)
    gemm_tc<128,128,2,4,ACT_RELU,1><<<dim3(HID/128, MTOT/128), 256, SMEM_BIG>>>(
        po1, dec_w1, dec_b1, ph2, MTOT, HID, DMODEL, DMODEL);

    // 10. dec2 -> out                    [16384,64] K=256   (tf32x3)
    gemm_tc<128,64,4,2,ACT_NONE,1><<<dim3(1, MTOT/128), 256, SMEM_NARR>>>(
        ph2, dec_w2, dec_b2, out, MTOT, DOUTD, HID, HID);
}

// round 4
// speedup vs baseline: 1.0099x; 1.0099x over previous
#include <cuda_runtime.h>
#include <math.h>
#include <stdint.h>

#define BATCH  8
#define SEQ    2048
#define MTOT   (BATCH*SEQ)      // 16384
#define DIN    64
#define HID    256
#define DMODEL 512
#define DINNER 1024
#define DSTATE 16
#define DTRANK 32
#define DCONV  4
#define DOUTD  64

// ---------------- scratch (allocation-free, __device__ globals) ----------------
__device__ float g_h    [MTOT*HID];
__device__ float g_u    [MTOT*DMODEL];
__device__ float g_xz   [MTOT*2*DINNER];   // (xm | z)
__device__ float g_xm   [MTOT*DINNER];
__device__ float g_dbl  [MTOT*64];         // [dt(32)|B(16)|C(16)]
__device__ float g_delta[MTOT*DINNER];
__device__ float g_y    [MTOT*DINNER];     // scan+gate out
__device__ float g_o1   [MTOT*DMODEL];
__device__ float g_h2   [MTOT*HID];

enum Act { ACT_NONE = 0, ACT_RELU = 1, ACT_SOFTPLUS = 2 };

// ---------------- helpers ----------------
__device__ __forceinline__ float to_tf32(float x) {
    float r;
    asm("cvt.rna.tf32.f32 %0, %1;" : "=f"(r) : "f"(x));
    return r;
}

__device__ __forceinline__ void mma8(float c[4], const uint32_t a[4], const uint32_t b[2]) {
    asm volatile(
        "mma.sync.aligned.m16n8k8.row.col.f32.tf32.tf32.f32 "
        "{%0,%1,%2,%3}, {%4,%5,%6,%7}, {%8,%9}, {%0,%1,%2,%3};\n"
        : "+f"(c[0]), "+f"(c[1]), "+f"(c[2]), "+f"(c[3])
        : "r"(a[0]), "r"(a[1]), "r"(a[2]), "r"(a[3]),
          "r"(b[0]), "r"(b[1]));
}

// ---------------- tensor-core GEMM with register double-buffering ----------------
// C[M,N] = act(A[M,K(lda)] * W[N,K]^T + bias)
// SPLIT=0: plain tf32.  SPLIT=1: tf32x3 (hi/lo split, fp32-class accuracy).
// tf32 conversion happens ONCE per element at smem-store time (R2 scheme).
// Global loads for tile kt+1 are issued into registers before computing tile kt.
template<int BM,int BN,int WARPS_M,int WARPS_N,int ACT,int SPLIT>
__global__ void __launch_bounds__(WARPS_M*WARPS_N*32)
gemm_tc(const float* __restrict__ A, const float* __restrict__ W,
        const float* __restrict__ bias, float* __restrict__ C,
        int M, int N, int K, int lda)
{
    constexpr int BK = 32, SK = BK + 4;
    constexpr int THREADS = WARPS_M*WARPS_N*32;
    constexpr int WM = BM/WARPS_M, WN = BN/WARPS_N;
    constexpr int MM = WM/16, MN = WN/8;
    constexpr int NBUF = SPLIT ? 2 : 1;
    constexpr int LA = (BM*(BK/4))/THREADS;   // float4 loads per thread (A)
    constexpr int LB = (BN*(BK/4))/THREADS;   // float4 loads per thread (B)

    extern __shared__ float sm[];
    float* sAh = sm;
    float* sAl = sAh + BM*SK;              // used if SPLIT
    float* sBh = sm + NBUF*BM*SK;
    float* sBl = sBh + BN*SK;              // used if SPLIT

    const int tid  = threadIdx.x;
    const int lane = tid & 31;
    const int warp = tid >> 5;
    const int g    = lane >> 2;
    const int c4   = lane & 3;
    const int wrow = (warp / WARPS_N) * WM;
    const int wcol = (warp % WARPS_N) * WN;
    const int bm   = blockIdx.y * BM;
    const int bn   = blockIdx.x * BN;

    float acc[MM][MN][4];
#pragma unroll
    for (int i = 0; i < MM; i++)
#pragma unroll
        for (int j = 0; j < MN; j++)
#pragma unroll
            for (int q = 0; q < 4; q++) acc[i][j][q] = 0.f;

    float4 ra[LA], rb[LB];

    auto ldg_tile = [&](int k0) {
#pragma unroll
        for (int u = 0; u < LA; u++) {
            int i  = tid + u*THREADS;
            int m  = i / (BK/4);
            int kc = (i % (BK/4)) * 4;
            ra[u] = *(const float4*)(A + (size_t)(bm + m)*lda + k0 + kc);
        }
#pragma unroll
        for (int u = 0; u < LB; u++) {
            int i  = tid + u*THREADS;
            int n  = i / (BK/4);
            int kc = (i % (BK/4)) * 4;
            rb[u] = *(const float4*)(W + (size_t)(bn + n)*K + k0 + kc);
        }
    };

    auto sts_tile = [&]() {
#pragma unroll
        for (int u = 0; u < LA; u++) {
            int i  = tid + u*THREADS;
            int m  = i / (BK/4);
            int kc = (i % (BK/4)) * 4;
            float4 v = ra[u];
            float4 h = make_float4(to_tf32(v.x), to_tf32(v.y), to_tf32(v.z), to_tf32(v.w));
            *(float4*)(sAh + m*SK + kc) = h;
            if (SPLIT) {
                float4 l = make_float4(to_tf32(v.x - h.x), to_tf32(v.y - h.y),
                                       to_tf32(v.z - h.z), to_tf32(v.w - h.w));
                *(float4*)(sAl + m*SK + kc) = l;
            }
        }
#pragma unroll
        for (int u = 0; u < LB; u++) {
            int i  = tid + u*THREADS;
            int n  = i / (BK/4);
            int kc = (i % (BK/4)) * 4;
            float4 v = rb[u];
            float4 h = make_float4(to_tf32(v.x), to_tf32(v.y), to_tf32(v.z), to_tf32(v.w));
            *(float4*)(sBh + n*SK + kc) = h;
            if (SPLIT) {
                float4 l = make_float4(to_tf32(v.x - h.x), to_tf32(v.y - h.y),
                                       to_tf32(v.z - h.z), to_tf32(v.w - h.w));
                *(float4*)(sBl + n*SK + kc) = l;
            }
        }
    };

    const int KT = K / BK;
    ldg_tile(0);

    for (int kt = 0; kt < KT; kt++) {
        sts_tile();                 // cvt + store current tile (from regs)
        __syncthreads();
        if (kt + 1 < KT)
            ldg_tile((kt + 1) * BK);   // prefetch next tile; completes during MMAs

#pragma unroll
        for (int kk = 0; kk < BK; kk += 8) {
            uint32_t ah[MM][4], al[MM][4];
#pragma unroll
            for (int mi = 0; mi < MM; mi++) {
                const float* p = sAh + (wrow + mi*16 + g)*SK + kk + c4;
                ah[mi][0] = __float_as_uint(p[0]);
                ah[mi][1] = __float_as_uint(p[8*SK]);
                ah[mi][2] = __float_as_uint(p[4]);
                ah[mi][3] = __float_as_uint(p[8*SK + 4]);
                if (SPLIT) {
                    const float* q = sAl + (wrow + mi*16 + g)*SK + kk + c4;
                    al[mi][0] = __float_as_uint(q[0]);
                    al[mi][1] = __float_as_uint(q[8*SK]);
                    al[mi][2] = __float_as_uint(q[4]);
                    al[mi][3] = __float_as_uint(q[8*SK + 4]);
                }
            }
#pragma unroll
            for (int ni = 0; ni < MN; ni++) {
                const float* p = sBh + (wcol + ni*8 + g)*SK + kk + c4;
                uint32_t bh[2] = { __float_as_uint(p[0]), __float_as_uint(p[4]) };
                uint32_t bl[2];
                if (SPLIT) {
                    const float* q = sBl + (wcol + ni*8 + g)*SK + kk + c4;
                    bl[0] = __float_as_uint(q[0]);
                    bl[1] = __float_as_uint(q[4]);
                }
#pragma unroll
                for (int mi = 0; mi < MM; mi++) {
                    if (SPLIT) {
                        mma8(acc[mi][ni], al[mi], bh);
                        mma8(acc[mi][ni], ah[mi], bl);
                    }
                    mma8(acc[mi][ni], ah[mi], bh);
                }
            }
        }
        __syncthreads();
    }

    // epilogue
#pragma unroll
    for (int mi = 0; mi < MM; mi++) {
        int r0 = bm + wrow + mi*16 + g;
#pragma unroll
        for (int ni = 0; ni < MN; ni++) {
            int col = bn + wcol + ni*8 + 2*c4;
            float b0 = 0.f, b1 = 0.f;
            if (bias) { b0 = bias[col]; b1 = bias[col + 1]; }
            float v0 = acc[mi][ni][0] + b0;
            float v1 = acc[mi][ni][1] + b1;
            float v2 = acc[mi][ni][2] + b0;
            float v3 = acc[mi][ni][3] + b1;
            if (ACT == ACT_RELU) {
                v0 = fmaxf(v0, 0.f); v1 = fmaxf(v1, 0.f);
                v2 = fmaxf(v2, 0.f); v3 = fmaxf(v3, 0.f);
            }
            if (ACT == ACT_SOFTPLUS) {
                v0 = (v0 > 20.f) ? v0 : log1pf(__expf(v0));
                v1 = (v1 > 20.f) ? v1 : log1pf(__expf(v1));
                v2 = (v2 > 20.f) ? v2 : log1pf(__expf(v2));
                v3 = (v3 > 20.f) ? v3 : log1pf(__expf(v3));
            }
            *(float2*)(C + (size_t)r0*N + col)       = make_float2(v0, v1);
            *(float2*)(C + (size_t)(r0 + 8)*N + col) = make_float2(v2, v3);
        }
    }
}

// ---------------- depthwise causal conv1d (k=4) + bias + SiLU (scalar, R2 form) ----------------
__global__ void conv_silu_kernel(const float* __restrict__ conv_w,
                                 const float* __restrict__ conv_b)
{
    int idx = blockIdx.x * blockDim.x + threadIdx.x;
    if (idx >= MTOT * DINNER) return;
    int d  = idx % DINNER;
    int bt = idx / DINNER;
    int t  = bt % SEQ;
    int b  = bt / SEQ;

    float acc = conv_b[d];
#pragma unroll
    for (int j = 0; j < DCONV; j++) {
        int tt = t - (DCONV - 1) + j;
        if (tt >= 0)
            acc = fmaf(conv_w[d*DCONV + j],
                       g_xz[(size_t)(b*SEQ + tt)*(2*DINNER) + d], acc);
    }
    float sv = acc / (1.f + __expf(-acc));     // silu
    g_xm[(size_t)bt*DINNER + d] = sv;
}

// ---------------- selective scan + fused gating ----------------
__global__ void scan_kernel(const float* __restrict__ A_log,
                            const float* __restrict__ D_param)
{
    int gid = blockIdx.x * blockDim.x + threadIdx.x;
    int grp = gid >> 4;          // (b,d)
    int s   = gid & 15;
    if (grp >= BATCH * DINNER) return;
    int b = grp / DINNER;
    int d = grp % DINNER;

    const float Av = -__expf(A_log[d*DSTATE + s]);
    const float Dv = D_param[d];
    const float* drow = g_delta + (size_t)b*SEQ*DINNER + d;
    const float* xrow = g_xm    + (size_t)b*SEQ*DINNER + d;
    const float* zrow = g_xz    + (size_t)b*SEQ*(2*DINNER) + DINNER + d;
    const float* dblb = g_dbl   + (size_t)b*SEQ*64;
    float*       yrow = g_y     + (size_t)b*SEQ*DINNER + d;

    float h = 0.f;
    for (int t = 0; t < SEQ; t++) {
        float dt = drow[(size_t)t*DINNER];
        float xt = xrow[(size_t)t*DINNER];
        float Bt = dblb[t*64 + DTRANK + s];
        float Ct = dblb[t*64 + DTRANK + DSTATE + s];
        float dA = __expf(dt * Av);
        h = fmaf(dA, h, dt * xt * Bt);
        float p = h * Ct;
        p += __shfl_xor_sync(0xffffffffu, p, 8, 16);
        p += __shfl_xor_sync(0xffffffffu, p, 4, 16);
        p += __shfl_xor_sync(0xffffffffu, p, 2, 16);
        p += __shfl_xor_sync(0xffffffffu, p, 1, 16);
        if (s == 0) {
            float z  = zrow[(size_t)t*2*DINNER];
            float yv = p + xt * Dv;
            yrow[(size_t)t*DINNER] = yv * (z / (1.f + __expf(-z)));
        }
    }
}

// ---------------- host launch ----------------
static float* sym_addr(const void* symbol)
{
    void* p = nullptr;
    cudaGetSymbolAddress(&p, symbol);
    return (float*)p;
}

extern "C" void kernel_launch(void* const* d_in, const int* in_sizes, int n_in,
                              void* d_out, int out_size)
{
    const float* x         = (const float*)d_in[0];
    const float* enc_w1    = (const float*)d_in[1];
    const float* enc_b1    = (const float*)d_in[2];
    const float* enc_w2    = (const float*)d_in[3];
    const float* enc_b2    = (const float*)d_in[4];
    const float* in_proj_w = (const float*)d_in[5];
    const float* conv_w    = (const float*)d_in[6];
    const float* conv_b    = (const float*)d_in[7];
    const float* x_proj_w  = (const float*)d_in[8];
    const float* dt_proj_w = (const float*)d_in[9];
    const float* dt_proj_b = (const float*)d_in[10];
    const float* A_log     = (const float*)d_in[11];
    const float* D_param   = (const float*)d_in[12];
    const float* out_proj_w= (const float*)d_in[13];
    const float* dec_w1    = (const float*)d_in[14];
    const float* dec_b1    = (const float*)d_in[15];
    const float* dec_w2    = (const float*)d_in[16];
    const float* dec_b2    = (const float*)d_in[17];
    float* out = (float*)d_out;

    float* ph    = sym_addr(g_h);
    float* pu    = sym_addr(g_u);
    float* pxz   = sym_addr(g_xz);
    float* pxm   = sym_addr(g_xm);
    float* pdbl  = sym_addr(g_dbl);
    float* pdel  = sym_addr(g_delta);
    float* py    = sym_addr(g_y);
    float* po1   = sym_addr(g_o1);
    float* ph2   = sym_addr(g_h2);

    // smem: (hi[,lo]) for A (BM rows) + B (BN rows), stride 36 floats
    const int SMEM_PLAIN_BIG   = (128 + 128) * 36 * 4;       // 36864
    const int SMEM_SPLIT_BIG   = 2 * (128 + 128) * 36 * 4;   // 73728
    const int SMEM_SPLIT_NARR  = 2 * (128 + 64) * 36 * 4;    // 55296

    cudaFuncSetAttribute(gemm_tc<128,128,2,4,ACT_RELU,1>,
                         cudaFuncAttributeMaxDynamicSharedMemorySize, SMEM_SPLIT_BIG);
    cudaFuncSetAttribute(gemm_tc<128,128,2,4,ACT_NONE,1>,
                         cudaFuncAttributeMaxDynamicSharedMemorySize, SMEM_SPLIT_BIG);
    cudaFuncSetAttribute(gemm_tc<128,128,2,4,ACT_SOFTPLUS,1>,
                         cudaFuncAttributeMaxDynamicSharedMemorySize, SMEM_SPLIT_BIG);
    cudaFuncSetAttribute(gemm_tc<128,64,4,2,ACT_NONE,1>,
                         cudaFuncAttributeMaxDynamicSharedMemorySize, SMEM_SPLIT_NARR);

    // 1. enc1: relu(x @ enc_w1^T + b1)   [16384,256] K=64   (tf32x3)
    gemm_tc<128,128,2,4,ACT_RELU,1><<<dim3(HID/128, MTOT/128), 256, SMEM_SPLIT_BIG>>>(
        x, enc_w1, enc_b1, ph, MTOT, HID, DIN, DIN);

    // 2. enc2: u = h @ enc_w2^T + b2     [16384,512] K=256  (tf32x3)
    gemm_tc<128,128,2,4,ACT_NONE,1><<<dim3(DMODEL/128, MTOT/128), 256, SMEM_SPLIT_BIG>>>(
        ph, enc_w2, enc_b2, pu, MTOT, DMODEL, HID, HID);

    // 3. in_proj: xz = u @ in_proj_w^T   [16384,2048] K=512 (plain tf32)
    gemm_tc<128,128,2,4,ACT_NONE,0><<<dim3(2*DINNER/128, MTOT/128), 256, SMEM_PLAIN_BIG>>>(
        pu, in_proj_w, nullptr, pxz, MTOT, 2*DINNER, DMODEL, DMODEL);

    // 4. conv + bias + silu -> g_xm
    conv_silu_kernel<<<(MTOT*DINNER)/256, 256>>>(conv_w, conv_b);

    // 5. x_proj: dbl = xm @ x_proj_w^T   [16384,64] K=1024  (tf32x3)
    gemm_tc<128,64,4,2,ACT_NONE,1><<<dim3(1, MTOT/128), 256, SMEM_SPLIT_NARR>>>(
        pxm, x_proj_w, nullptr, pdbl, MTOT, 64, DINNER, DINNER);

    // 6. dt_proj + softplus: delta       [16384,1024] K=32, lda=64 (tf32x3)
    gemm_tc<128,128,2,4,ACT_SOFTPLUS,1><<<dim3(DINNER/128, MTOT/128), 256, SMEM_SPLIT_BIG>>>(
        pdbl, dt_proj_w, dt_proj_b, pdel, MTOT, DINNER, DTRANK, 64);

    // 7. selective scan + fused gating -> g_y
    scan_kernel<<<(BATCH*DINNER*DSTATE)/256, 256>>>(A_log, D_param);

    // 8. out_proj: o1 = y @ out_proj_w^T [16384,512] K=1024 (plain tf32)
    gemm_tc<128,128,2,4,ACT_NONE,0><<<dim3(DMODEL/128, MTOT/128), 256, SMEM_PLAIN_BIG>>>(
        py, out_proj_w, nullptr, po1, MTOT, DMODEL, DINNER, DINNER);

    // 9. dec1: relu                      [16384,256] K=512  (tf32x3)
    gemm_tc<128,128,2,4,ACT_RELU,1><<<dim3(HID/128, MTOT/128), 256, SMEM_SPLIT_BIG>>>(
        po1, dec_w1, dec_b1, ph2, MTOT, HID, DMODEL, DMODEL);

    // 10. dec2 -> out                    [16384,64] K=256   (tf32x3)
    gemm_tc<128,64,4,2,ACT_NONE,1><<<dim3(1, MTOT/128), 256, SMEM_SPLIT_NARR>>>(
        ph2, dec_w2, dec_b2, out, MTOT, DOUTD, HID, HID);
}